// round 14
// baseline (speedup 1.0000x reference)
#include <cuda_runtime.h>
#include <cstdint>

// Problem constants
#define B_TOTAL  128
#define C_IN     32
#define C_OUT    8
#define S_TOTAL  8192

// Tiling
#define S_TILE    32     // s-values per block = 8 float4 groups
#define SG        8      // float4 groups per block
#define B_CHUNK   32     // batches per chunk (2 per thread)
#define N_CHUNKS  2      // chunks per block -> 64 batches per block
#define THREADS   128

typedef unsigned long long ull;

// ---------------------------------------------------------------------------
// helpers
// ---------------------------------------------------------------------------
__device__ __forceinline__ float tanh_fast(float x) {
    float y;
    asm("tanh.approx.f32 %0, %1;" : "=f"(y) : "f"(x));
    return y;
}

__device__ __forceinline__ float4 ld4(const float* p) {
    return *reinterpret_cast<const float4*>(p);
}

__device__ __forceinline__ float4 tanh4_of_prod(float4 a, float4 b) {
    float4 r;
    r.x = tanh_fast(a.x * b.x);
    r.y = tanh_fast(a.y * b.y);
    r.z = tanh_fast(a.z * b.z);
    r.w = tanh_fast(a.w * b.w);
    return r;
}

// packed f32x2 FMA (Blackwell FFMA2, PTX-only)
__device__ __forceinline__ void fma2p(ull& acc, ull h, ull w) {
    asm("fma.rn.f32x2 %0, %1, %2, %0;" : "+l"(acc) : "l"(h), "l"(w));
}

struct u2 { ull lo, hi; };   // 4 packed floats (== float4 bits)

__device__ __forceinline__ void fma4p(u2& acc, const u2& h, const u2& w) {
    fma2p(acc.lo, h.lo, w.lo);
    fma2p(acc.hi, h.hi, w.hi);
}

// ---------------------------------------------------------------------------
// Single fused kernel, persistent over 2 batch-chunks.
//
// grid = (256 s-tiles, 2 batch-groups) = 512 CTAs <= 592 slots -> ONE wave.
// Preamble (once per block):
//   w2s = w2 tile (16 LDG.128/thread), wss[j][sg] = sum_i w1[i][j][s4]
// Then 2 chunks of 32 batches; per thread 2 batches/chunk:
//   per j: 2 LDG.128 (x), 1 LDS.128 (ws), 8 LDS.128 (w2) -> 32 FFMA2
// Outer tanh via tanh.approx.
// __launch_bounds__(128, 4): 128 regs -> 4 CTAs/SM.
// ---------------------------------------------------------------------------
__global__ void __launch_bounds__(THREADS, 4) fused_kernel(
    const float* __restrict__ x,     // [B][C_IN][S]
    const float* __restrict__ w1,    // [C_IN][C_IN][S]
    const float* __restrict__ w2,    // [C_OUT][C_IN][S]
    const float* __restrict__ bias,  // [C_OUT][S]
    float* __restrict__ out)         // [B][C_OUT][S]
{
    __shared__ float4 w2s[C_OUT * C_IN * SG];  // 2048 f4 = 32 KB
    __shared__ float4 wss[C_IN * SG];          //  256 f4 =  4 KB

    const int t     = threadIdx.x;
    const int sBase = blockIdx.x * S_TILE;
    const int bt    = t >> 3;                  // 0..15
    const int sg    = t & 7;                   // 0..7
    const int bBase = blockIdx.y * (B_CHUNK * N_CHUNKS);   // 0 or 64

    // ---- preamble A: w2 tile -> smem ----
#pragma unroll
    for (int k = 0; k < (C_OUT * C_IN * SG) / THREADS; k++) {   // 16 iters
        int idx = t + k * THREADS;
        int row = idx >> 3;           // o*32 + j
        int sgl = idx & 7;
        w2s[idx] = ld4(w2 + (size_t)row * S_TOTAL + sBase + sgl * 4);
    }

    // ---- preamble B: ws tile computed from w1 (reduction over i) ----
#pragma unroll
    for (int k = 0; k < (C_IN * SG) / THREADS; k++) {           // 2 iters
        int idx = t + k * THREADS;
        int j   = idx >> 3;
        int sgl = idx & 7;
        const float* p = w1 + (size_t)j * S_TOTAL + sBase + sgl * 4;
        float4 a = make_float4(0.f, 0.f, 0.f, 0.f);
#pragma unroll 8
        for (int i = 0; i < C_IN; i++) {
            float4 v = ld4(p + (size_t)i * C_IN * S_TOTAL);
            a.x += v.x; a.y += v.y; a.z += v.z; a.w += v.w;
        }
        wss[idx] = a;
    }
    __syncthreads();

    // ---- chunk loop (NOT unrolled: keeps acc pressure at one chunk) ----
#pragma unroll 1
    for (int bc = 0; bc < N_CHUNKS; bc++) {
        const int b0 = bBase + bc * B_CHUNK + bt;
        const int b1 = b0 + 16;

        // accumulators init from bias (same bias for both batches)
        u2 acc0[C_OUT], acc1[C_OUT];
#pragma unroll
        for (int o = 0; o < C_OUT; o++) {
            float4 bv = ld4(bias + (size_t)o * S_TOTAL + sBase + sg * 4);
            acc0[o] = *reinterpret_cast<const u2*>(&bv);
            acc1[o] = acc0[o];
        }

        // main loop over j
        const float* xp0 = x + ((size_t)b0 * C_IN) * S_TOTAL + sBase + sg * 4;
        const float* xp1 = x + ((size_t)b1 * C_IN) * S_TOTAL + sBase + sg * 4;
#pragma unroll 4
        for (int j = 0; j < C_IN; j++) {
            float4 xv0 = ld4(xp0 + (size_t)j * S_TOTAL);
            float4 xv1 = ld4(xp1 + (size_t)j * S_TOTAL);
            float4 wsv = wss[j * SG + sg];
            float4 h0f = tanh4_of_prod(xv0, wsv);
            float4 h1f = tanh4_of_prod(xv1, wsv);
            u2 h0 = *reinterpret_cast<const u2*>(&h0f);
            u2 h1 = *reinterpret_cast<const u2*>(&h1f);
#pragma unroll
            for (int o = 0; o < C_OUT; o++) {
                u2 w = *reinterpret_cast<const u2*>(&w2s[(o * C_IN + j) * SG + sg]);
                fma4p(acc0[o], h0, w);
                fma4p(acc1[o], h1, w);
            }
        }

        // epilogue: outer tanh (approx) + store (both batches)
        float* op0 = out + ((size_t)b0 * C_OUT) * S_TOTAL + sBase + sg * 4;
        float* op1 = out + ((size_t)b1 * C_OUT) * S_TOTAL + sBase + sg * 4;
#pragma unroll
        for (int o = 0; o < C_OUT; o++) {
            float4 a0 = *reinterpret_cast<const float4*>(&acc0[o]);
            float4 ov;
            ov.x = tanh_fast(a0.x);
            ov.y = tanh_fast(a0.y);
            ov.z = tanh_fast(a0.z);
            ov.w = tanh_fast(a0.w);
            *reinterpret_cast<float4*>(op0 + (size_t)o * S_TOTAL) = ov;
            float4 a1 = *reinterpret_cast<const float4*>(&acc1[o]);
            float4 ov1;
            ov1.x = tanh_fast(a1.x);
            ov1.y = tanh_fast(a1.y);
            ov1.z = tanh_fast(a1.z);
            ov1.w = tanh_fast(a1.w);
            *reinterpret_cast<float4*>(op1 + (size_t)o * S_TOTAL) = ov1;
        }
    }
}

// ---------------------------------------------------------------------------
// launch
// ---------------------------------------------------------------------------
extern "C" void kernel_launch(void* const* d_in, const int* in_sizes, int n_in,
                              void* d_out, int out_size) {
    const float* x    = (const float*)d_in[0];
    const float* w1   = (const float*)d_in[1];
    const float* w2   = (const float*)d_in[2];
    const float* bias = (const float*)d_in[3];
    float* out = (float*)d_out;

    // (256 s-tiles, 2 batch-groups) = 512 blocks -> single wave on 148 SMs x 4
    dim3 grid(S_TOTAL / S_TILE, B_TOTAL / (B_CHUNK * N_CHUNKS));
    fused_kernel<<<grid, THREADS>>>(x, w1, w2, bias, out);
}

// round 15
// speedup vs baseline: 1.0904x; 1.0904x over previous
#include <cuda_runtime.h>
#include <cstdint>

// Problem constants
#define B_TOTAL  128
#define C_IN     32
#define C_OUT    8
#define S_TOTAL  8192

// Tiling
#define S_TILE    32     // s-values per block = 8 float4 groups
#define SG        8      // float4 groups per block
#define B_PER_BLK 32     // batches per block (2 per thread)
#define THREADS   128

#define PF_DIST   8      // x prefetch distance in j-steps

typedef unsigned long long ull;

// ---------------------------------------------------------------------------
// helpers
// ---------------------------------------------------------------------------
__device__ __forceinline__ float tanh_fast(float x) {
    float y;
    asm("tanh.approx.f32 %0, %1;" : "=f"(y) : "f"(x));
    return y;
}

__device__ __forceinline__ float4 ld4(const float* p) {
    return *reinterpret_cast<const float4*>(p);
}

__device__ __forceinline__ void prefetch_l2(const void* p) {
    asm volatile("prefetch.global.L2 [%0];" :: "l"(p));
}

__device__ __forceinline__ float4 tanh4_of_prod(float4 a, float4 b) {
    float4 r;
    r.x = tanh_fast(a.x * b.x);
    r.y = tanh_fast(a.y * b.y);
    r.z = tanh_fast(a.z * b.z);
    r.w = tanh_fast(a.w * b.w);
    return r;
}

// packed f32x2 FMA (Blackwell FFMA2, PTX-only)
__device__ __forceinline__ void fma2p(ull& acc, ull h, ull w) {
    asm("fma.rn.f32x2 %0, %1, %2, %0;" : "+l"(acc) : "l"(h), "l"(w));
}

struct u2 { ull lo, hi; };   // 4 packed floats (== float4 bits)

__device__ __forceinline__ void fma4p(u2& acc, const u2& h, const u2& w) {
    fma2p(acc.lo, h.lo, w.lo);
    fma2p(acc.hi, h.hi, w.hi);
}

// ---------------------------------------------------------------------------
// Single fused kernel: ws reduction (preamble) + stage1 + stage2.
// R13 structure (1024 CTAs, 128 regs, 4 CTAs/SM) + rolling L2 prefetch of x.
//
// Mainloop per thread (2 batches), per j:
//   2 LDG.128 (x, L2-warmed by prefetch), 1 LDS.128 (ws), 8 LDS.128 (w2),
//   2 prefetch.global.L2 (x at j+PF_DIST) -> 32 FFMA2
// ---------------------------------------------------------------------------
__global__ void __launch_bounds__(THREADS, 4) fused_kernel(
    const float* __restrict__ x,     // [B][C_IN][S]
    const float* __restrict__ w1,    // [C_IN][C_IN][S]
    const float* __restrict__ w2,    // [C_OUT][C_IN][S]
    const float* __restrict__ bias,  // [C_OUT][S]
    float* __restrict__ out)         // [B][C_OUT][S]
{
    __shared__ float4 w2s[C_OUT * C_IN * SG];  // 2048 f4 = 32 KB
    __shared__ float4 wss[C_IN * SG];          //  256 f4 =  4 KB

    const int t     = threadIdx.x;
    const int sBase = blockIdx.x * S_TILE;
    const int bt    = t >> 3;                  // 0..15
    const int sg    = t & 7;                   // 0..7
    const int b0    = blockIdx.y * B_PER_BLK + bt;
    const int b1    = b0 + 16;

    const float* xp0 = x + ((size_t)b0 * C_IN) * S_TOTAL + sBase + sg * 4;
    const float* xp1 = x + ((size_t)b1 * C_IN) * S_TOTAL + sBase + sg * 4;

    // warm L2 for the first PF_DIST j-steps of x while the preamble runs
#pragma unroll
    for (int j = 0; j < PF_DIST; j++) {
        prefetch_l2(xp0 + (size_t)j * S_TOTAL);
        prefetch_l2(xp1 + (size_t)j * S_TOTAL);
    }

    // ---- preamble A: w2 tile -> smem ----
#pragma unroll
    for (int k = 0; k < (C_OUT * C_IN * SG) / THREADS; k++) {   // 16 iters
        int idx = t + k * THREADS;
        int row = idx >> 3;           // o*32 + j
        int sgl = idx & 7;
        w2s[idx] = ld4(w2 + (size_t)row * S_TOTAL + sBase + sgl * 4);
    }

    // ---- preamble B: ws tile computed from w1 (reduction over i) ----
#pragma unroll
    for (int k = 0; k < (C_IN * SG) / THREADS; k++) {           // 2 iters
        int idx = t + k * THREADS;
        int j   = idx >> 3;
        int sgl = idx & 7;
        const float* p = w1 + (size_t)j * S_TOTAL + sBase + sgl * 4;
        float4 a = make_float4(0.f, 0.f, 0.f, 0.f);
#pragma unroll 8
        for (int i = 0; i < C_IN; i++) {
            float4 v = ld4(p + (size_t)i * C_IN * S_TOTAL);
            a.x += v.x; a.y += v.y; a.z += v.z; a.w += v.w;
        }
        wss[idx] = a;
    }
    __syncthreads();

    // ---- accumulators init from bias (same bias for both batches) ----
    u2 acc0[C_OUT], acc1[C_OUT];
#pragma unroll
    for (int o = 0; o < C_OUT; o++) {
        float4 bv = ld4(bias + (size_t)o * S_TOTAL + sBase + sg * 4);
        acc0[o] = *reinterpret_cast<const u2*>(&bv);
        acc1[o] = acc0[o];
    }

    // ---- main loop over j with rolling L2 prefetch ----
#pragma unroll 4
    for (int j = 0; j < C_IN; j++) {
        // prefetch x for j + PF_DIST (uniform predicate, cheap)
        if (j + PF_DIST < C_IN) {
            prefetch_l2(xp0 + (size_t)(j + PF_DIST) * S_TOTAL);
            prefetch_l2(xp1 + (size_t)(j + PF_DIST) * S_TOTAL);
        }
        float4 xv0 = ld4(xp0 + (size_t)j * S_TOTAL);
        float4 xv1 = ld4(xp1 + (size_t)j * S_TOTAL);
        float4 wsv = wss[j * SG + sg];
        float4 h0f = tanh4_of_prod(xv0, wsv);
        float4 h1f = tanh4_of_prod(xv1, wsv);
        u2 h0 = *reinterpret_cast<const u2*>(&h0f);
        u2 h1 = *reinterpret_cast<const u2*>(&h1f);
#pragma unroll
        for (int o = 0; o < C_OUT; o++) {
            u2 w = *reinterpret_cast<const u2*>(&w2s[(o * C_IN + j) * SG + sg]);
            fma4p(acc0[o], h0, w);
            fma4p(acc1[o], h1, w);
        }
    }

    // ---- epilogue: outer tanh (approx) + store (both batches) ----
    float* op0 = out + ((size_t)b0 * C_OUT) * S_TOTAL + sBase + sg * 4;
    float* op1 = out + ((size_t)b1 * C_OUT) * S_TOTAL + sBase + sg * 4;
#pragma unroll
    for (int o = 0; o < C_OUT; o++) {
        float4 a0 = *reinterpret_cast<const float4*>(&acc0[o]);
        float4 ov;
        ov.x = tanh_fast(a0.x);
        ov.y = tanh_fast(a0.y);
        ov.z = tanh_fast(a0.z);
        ov.w = tanh_fast(a0.w);
        *reinterpret_cast<float4*>(op0 + (size_t)o * S_TOTAL) = ov;
        float4 a1 = *reinterpret_cast<const float4*>(&acc1[o]);
        float4 ov1;
        ov1.x = tanh_fast(a1.x);
        ov1.y = tanh_fast(a1.y);
        ov1.z = tanh_fast(a1.z);
        ov1.w = tanh_fast(a1.w);
        *reinterpret_cast<float4*>(op1 + (size_t)o * S_TOTAL) = ov1;
    }
}

// ---------------------------------------------------------------------------
// launch
// ---------------------------------------------------------------------------
extern "C" void kernel_launch(void* const* d_in, const int* in_sizes, int n_in,
                              void* d_out, int out_size) {
    const float* x    = (const float*)d_in[0];
    const float* w1   = (const float*)d_in[1];
    const float* w2   = (const float*)d_in[2];
    const float* bias = (const float*)d_in[3];
    float* out = (float*)d_out;

    dim3 grid(S_TOTAL / S_TILE, B_TOTAL / B_PER_BLK);   // (256, 4) = 1024 blocks
    fused_kernel<<<grid, THREADS>>>(x, w1, w2, bias, out);
}

// round 16
// speedup vs baseline: 1.2772x; 1.1713x over previous
#include <cuda_runtime.h>
#include <cstdint>

// Problem constants
#define B_TOTAL  128
#define C_IN     32
#define C_OUT    8
#define S_TOTAL  8192

// Tiling
#define S_TILE    32     // s-values per block = 8 float4 groups
#define SG        8      // float4 groups per block
#define B_PER_BLK 32     // batches per block (2 per thread)
#define THREADS   128
#define DEPTH     3      // cp.async pipeline stages for x

typedef unsigned long long ull;

// ---------------------------------------------------------------------------
// helpers
// ---------------------------------------------------------------------------
__device__ __forceinline__ float tanh_fast(float x) {
    float y;
    asm("tanh.approx.f32 %0, %1;" : "=f"(y) : "f"(x));
    return y;
}

__device__ __forceinline__ float4 ld4(const float* p) {
    return *reinterpret_cast<const float4*>(p);
}

__device__ __forceinline__ float4 tanh4_of_prod(float4 a, float4 b) {
    float4 r;
    r.x = tanh_fast(a.x * b.x);
    r.y = tanh_fast(a.y * b.y);
    r.z = tanh_fast(a.z * b.z);
    r.w = tanh_fast(a.w * b.w);
    return r;
}

// packed f32x2 FMA (Blackwell FFMA2, PTX-only)
__device__ __forceinline__ void fma2p(ull& acc, ull h, ull w) {
    asm("fma.rn.f32x2 %0, %1, %2, %0;" : "+l"(acc) : "l"(h), "l"(w));
}

struct u2 { ull lo, hi; };   // 4 packed floats (== float4 bits)

__device__ __forceinline__ void fma4p(u2& acc, const u2& h, const u2& w) {
    fma2p(acc.lo, h.lo, w.lo);
    fma2p(acc.hi, h.hi, w.hi);
}

// cp.async 16B global -> shared (LDGSTS)
__device__ __forceinline__ void cp16(uint32_t dst, const float* src) {
    asm volatile("cp.async.ca.shared.global [%0], [%1], 16;"
                 :: "r"(dst), "l"(src) : "memory");
}
#define CP_COMMIT() asm volatile("cp.async.commit_group;" ::: "memory")
#define CP_WAIT2()  asm volatile("cp.async.wait_group 2;"  ::: "memory")

// ---------------------------------------------------------------------------
// Single fused kernel: ws reduction (preamble) + stage1 + stage2.
// R13 structure (1024 CTAs, 4 CTAs/SM) + 3-stage cp.async pipeline for x.
//
// Mainloop per thread (2 batches), per j:
//   issue 2 cp.async 16B (x at j+2) -> commit -> wait_group 2 (g(j) done)
//   2 LDS.128 (x from stage), 1 LDS.128 (ws), 8 LDS.128 (w2) -> 32 FFMA2
// Smem: 32 KB (w2) + 4 KB (ws) + 12 KB (x stages) = 48 KB exactly.
// ---------------------------------------------------------------------------
__global__ void __launch_bounds__(THREADS, 4) fused_kernel(
    const float* __restrict__ x,     // [B][C_IN][S]
    const float* __restrict__ w1,    // [C_IN][C_IN][S]
    const float* __restrict__ w2,    // [C_OUT][C_IN][S]
    const float* __restrict__ bias,  // [C_OUT][S]
    float* __restrict__ out)         // [B][C_OUT][S]
{
    __shared__ float4 w2s[C_OUT * C_IN * SG];      // 2048 f4 = 32 KB
    __shared__ float4 wss[C_IN * SG];              //  256 f4 =  4 KB
    __shared__ float4 xs[DEPTH][B_PER_BLK][SG];    //  768 f4 = 12 KB

    const int t     = threadIdx.x;
    const int sBase = blockIdx.x * S_TILE;
    const int bt    = t >> 3;                  // 0..15
    const int sg    = t & 7;                   // 0..7
    const int b0    = blockIdx.y * B_PER_BLK + bt;
    const int b1    = b0 + 16;

    const float* xp0 = x + ((size_t)b0 * C_IN) * S_TOTAL + sBase + sg * 4;
    const float* xp1 = x + ((size_t)b1 * C_IN) * S_TOTAL + sBase + sg * 4;

    // per-thread stage-0 write/read addresses (stage stride 4096 B,
    // b1 slot offset 2048 B)
    const uint32_t xw = (uint32_t)__cvta_generic_to_shared(&xs[0][bt][sg]);

    // ---- x pipeline prologue: stages 0,1 (overlap the preamble below) ----
    cp16(xw,            xp0);
    cp16(xw + 2048,     xp1);
    CP_COMMIT();
    cp16(xw + 4096,         xp0 + S_TOTAL);
    cp16(xw + 4096 + 2048,  xp1 + S_TOTAL);
    CP_COMMIT();

    // ---- preamble A: w2 tile -> smem ----
#pragma unroll
    for (int k = 0; k < (C_OUT * C_IN * SG) / THREADS; k++) {   // 16 iters
        int idx = t + k * THREADS;
        int row = idx >> 3;           // o*32 + j
        int sgl = idx & 7;
        w2s[idx] = ld4(w2 + (size_t)row * S_TOTAL + sBase + sgl * 4);
    }

    // ---- preamble B: ws tile computed from w1 (reduction over i) ----
#pragma unroll
    for (int k = 0; k < (C_IN * SG) / THREADS; k++) {           // 2 iters
        int idx = t + k * THREADS;
        int j   = idx >> 3;
        int sgl = idx & 7;
        const float* p = w1 + (size_t)j * S_TOTAL + sBase + sgl * 4;
        float4 a = make_float4(0.f, 0.f, 0.f, 0.f);
#pragma unroll 8
        for (int i = 0; i < C_IN; i++) {
            float4 v = ld4(p + (size_t)i * C_IN * S_TOTAL);
            a.x += v.x; a.y += v.y; a.z += v.z; a.w += v.w;
        }
        wss[idx] = a;
    }
    __syncthreads();

    // ---- accumulators init from bias (same bias for both batches) ----
    u2 acc0[C_OUT], acc1[C_OUT];
#pragma unroll
    for (int o = 0; o < C_OUT; o++) {
        float4 bv = ld4(bias + (size_t)o * S_TOTAL + sBase + sg * 4);
        acc0[o] = *reinterpret_cast<const u2*>(&bv);
        acc1[o] = acc0[o];
    }

    // ---- main loop over j with cp.async pipeline ----
    int st = 0;                       // stage holding x(j)
#pragma unroll 1
    for (int j = 0; j < C_IN; j++) {
        // issue x(j+2) into the stage freed at iter j-1
        if (j + 2 < C_IN) {
            int st2 = st + 2; if (st2 >= DEPTH) st2 -= DEPTH;
            uint32_t w = xw + st2 * 4096;
            cp16(w,        xp0 + (size_t)(j + 2) * S_TOTAL);
            cp16(w + 2048, xp1 + (size_t)(j + 2) * S_TOTAL);
        }
        CP_COMMIT();                  // empty in the 2 tail iterations
        CP_WAIT2();                   // guarantees group g(j) complete

        float4 xv0 = xs[st][bt][sg];
        float4 xv1 = xs[st][bt + 16][sg];
        float4 wsv = wss[j * SG + sg];
        float4 h0f = tanh4_of_prod(xv0, wsv);
        float4 h1f = tanh4_of_prod(xv1, wsv);
        u2 h0 = *reinterpret_cast<const u2*>(&h0f);
        u2 h1 = *reinterpret_cast<const u2*>(&h1f);
#pragma unroll
        for (int o = 0; o < C_OUT; o++) {
            u2 w = *reinterpret_cast<const u2*>(&w2s[(o * C_IN + j) * SG + sg]);
            fma4p(acc0[o], h0, w);
            fma4p(acc1[o], h1, w);
        }
        st++; if (st >= DEPTH) st = 0;
    }

    // ---- epilogue: outer tanh (approx) + store (both batches) ----
    float* op0 = out + ((size_t)b0 * C_OUT) * S_TOTAL + sBase + sg * 4;
    float* op1 = out + ((size_t)b1 * C_OUT) * S_TOTAL + sBase + sg * 4;
#pragma unroll
    for (int o = 0; o < C_OUT; o++) {
        float4 a0 = *reinterpret_cast<const float4*>(&acc0[o]);
        float4 ov;
        ov.x = tanh_fast(a0.x);
        ov.y = tanh_fast(a0.y);
        ov.z = tanh_fast(a0.z);
        ov.w = tanh_fast(a0.w);
        *reinterpret_cast<float4*>(op0 + (size_t)o * S_TOTAL) = ov;
        float4 a1 = *reinterpret_cast<const float4*>(&acc1[o]);
        float4 ov1;
        ov1.x = tanh_fast(a1.x);
        ov1.y = tanh_fast(a1.y);
        ov1.z = tanh_fast(a1.z);
        ov1.w = tanh_fast(a1.w);
        *reinterpret_cast<float4*>(op1 + (size_t)o * S_TOTAL) = ov1;
    }
}

// ---------------------------------------------------------------------------
// launch
// ---------------------------------------------------------------------------
extern "C" void kernel_launch(void* const* d_in, const int* in_sizes, int n_in,
                              void* d_out, int out_size) {
    const float* x    = (const float*)d_in[0];
    const float* w1   = (const float*)d_in[1];
    const float* w2   = (const float*)d_in[2];
    const float* bias = (const float*)d_in[3];
    float* out = (float*)d_out;

    dim3 grid(S_TOTAL / S_TILE, B_TOTAL / B_PER_BLK);   // (256, 4) = 1024 blocks
    fused_kernel<<<grid, THREADS>>>(x, w1, w2, bias, out);
}